// round 16
// baseline (speedup 1.0000x reference)
#include <cuda_runtime.h>
#include <cstdint>

#define GNUM 40
#define NN   2000
#define E0   16000
#define ET   18000
#define TT   10
#define BB   4
#define KC   512
#define NCHUNK 125

// ---------------- scratch ----------------
__device__ float  g_xl[GNUM * NN * 128];
__device__ float  g_xr[GNUM * NN * 128];
__device__ float  g_hA[GNUM * NN * 128];
__device__ float  g_hB[GNUM * NN * 128];
__device__ int    g_rowstart[NN + 1];
__device__ float4 g_psea[ET];              // (bitcast src, ea.x, ea.y, 0)
__device__ float  g_gates[GNUM * 1024];
__device__ float  g_part[NCHUNK * 1024 * GNUM];
__device__ float  g_gacc[BB * 1024];
__device__ float  g_whht[256 * 1024];
__device__ float  g_c8[BB * 256];
__device__ int    g_ctr;

// ---------------- tf32 helpers ----------------
__device__ __forceinline__ uint32_t f2tf(float v) {
    uint32_t r; asm("cvt.rna.tf32.f32 %0, %1;" : "=r"(r) : "f"(v)); return r;
}
__device__ __forceinline__ void split2(float v, float& hi, float& lo) {
    hi = __uint_as_float(f2tf(v));
    lo = __uint_as_float(f2tf(v - hi));
}
__device__ __forceinline__ void mma8(float (&c)[4], const uint32_t (&a)[4],
                                     uint32_t b0, uint32_t b1) {
    asm volatile(
        "mma.sync.aligned.m16n8k8.row.col.f32.tf32.tf32.f32 "
        "{%0,%1,%2,%3},{%4,%5,%6,%7},{%8,%9},{%0,%1,%2,%3};"
        : "+f"(c[0]), "+f"(c[1]), "+f"(c[2]), "+f"(c[3])
        : "r"(a[0]), "r"(a[1]), "r"(a[2]), "r"(a[3]), "r"(b0), "r"(b1));
}

// ---------------- fused prep (1 block) ----------------
__global__ void __launch_bounds__(1024) k_prep_all(const int* __restrict__ ei,
                                                   const float* __restrict__ ea) {
    __shared__ int   sdeg[NN];
    __shared__ int   sscan[1024];
    __shared__ float r0[1024], r1[1024];
    __shared__ float2 smean;
    int t = threadIdx.x;
    float a = 0.f, b = 0.f;
    for (int e = t; e < E0; e += 1024) { a += ea[2 * e]; b += ea[2 * e + 1]; }
    r0[t] = a; r1[t] = b;
    for (int i = t; i < NN; i += 1024) sdeg[i] = 0;
    __syncthreads();
    for (int o = 512; o; o >>= 1) {
        if (t < o) { r0[t] += r0[t + o]; r1[t] += r1[t + o]; }
        __syncthreads();
    }
    if (t == 0) { smean.x = r0[0] / E0; smean.y = r1[0] / E0; }
    for (int e = t; e < ET; e += 1024) {
        int d = (e < E0) ? ei[E0 + e] : (e - E0);
        atomicAdd(&sdeg[d], 1);
    }
    __syncthreads();
    int i0 = 2 * t, i1 = 2 * t + 1;
    int v0 = (i0 < NN) ? sdeg[i0] : 0;
    int v1 = (i1 < NN) ? sdeg[i1] : 0;
    int tot = v0 + v1;
    sscan[t] = tot;
    __syncthreads();
    for (int off = 1; off < 1024; off <<= 1) {
        int x = (t >= off) ? sscan[t - off] : 0;
        __syncthreads();
        sscan[t] += x;
        __syncthreads();
    }
    int base = sscan[t] - tot;
    __syncthreads();
    if (i0 < NN) { g_rowstart[i0] = base;      sdeg[i0] = base; }
    if (i1 < NN) { g_rowstart[i1] = base + v0; sdeg[i1] = base + v0; }
    if (t == 1023) g_rowstart[NN] = sscan[1023];
    __syncthreads();
    float2 mn = smean;
    for (int e = t; e < ET; e += 1024) {
        int s, d;
        if (e < E0) { s = ei[e]; d = ei[E0 + e]; }
        else        { s = d = e - E0; }
        int pos = atomicAdd(&sdeg[d], 1);
        float2 v;
        if (e < E0) { v.x = ea[2 * e]; v.y = ea[2 * e + 1]; }
        else        v = mn;
        g_psea[pos] = make_float4(__int_as_float(s), v.x, v.y, 0.f);
    }
}

// ---------------- whh transpose + barrier counter reset ----------------
__global__ void k_whht(const float* __restrict__ whh) {
    int i = blockIdx.x * 256 + threadIdx.x;
    int j = i >> 8, k = i & 255;
    g_whht[k * 1024 + j] = whh[i];
    if (i == 0) g_ctr = 0;
}

// ---------------- fp32 GEMM N=128 (layer 0, K=8) ----------------
__global__ void __launch_bounds__(256) k_gemm_n128(const float* __restrict__ A,
                            const float* __restrict__ B0, const float* __restrict__ B1,
                            float* __restrict__ C0, float* __restrict__ C1, int K) {
    const float* B = blockIdx.z ? B1 : B0;
    float*       C = blockIdx.z ? C1 : C0;
    __shared__ float As[8][128];
    __shared__ float Bs[8][128];
    int tid = threadIdx.x;
    int m0 = blockIdx.y * 128;
    int arow = tid >> 1, acol4 = (tid & 1) * 4;
    int brow = tid >> 5, bcol = (tid & 31) * 4;
    int tx = tid & 15, ty = tid >> 4;
    const float* Ap = A + (size_t)(m0 + arow) * K + acol4;
    float4 av = *(const float4*)Ap;
    float4 bv = *(const float4*)(B + (size_t)brow * 128 + bcol);
    float acc[8][8] = {};
    for (int k0 = 0; k0 < K; k0 += 8) {
        As[acol4 + 0][arow] = av.x; As[acol4 + 1][arow] = av.y;
        As[acol4 + 2][arow] = av.z; As[acol4 + 3][arow] = av.w;
        *(float4*)&Bs[brow][bcol] = bv;
        __syncthreads();
        if (k0 + 8 < K) {
            av = *(const float4*)(Ap + k0 + 8);
            bv = *(const float4*)(B + (size_t)(k0 + 8 + brow) * 128 + bcol);
        }
#pragma unroll
        for (int kk = 0; kk < 8; kk++) {
            float a[8], b[8];
            *(float4*)a       = *(const float4*)&As[kk][ty * 8];
            *(float4*)(a + 4) = *(const float4*)&As[kk][ty * 8 + 4];
            *(float4*)b       = *(const float4*)&Bs[kk][tx * 8];
            *(float4*)(b + 4) = *(const float4*)&Bs[kk][tx * 8 + 4];
#pragma unroll
            for (int i = 0; i < 8; i++)
#pragma unroll
                for (int j = 0; j < 8; j++) acc[i][j] += a[i] * b[j];
        }
        __syncthreads();
    }
#pragma unroll
    for (int i = 0; i < 8; i++) {
        float* cp = C + (size_t)(m0 + ty * 8 + i) * 128 + tx * 8;
        *(float4*)cp       = *(float4*)&acc[i][0];
        *(float4*)(cp + 4) = *(float4*)&acc[i][4];
    }
}

// ---------------- tf32 split-mma GEMM N=128 ----------------
__global__ void __launch_bounds__(256) k_gemm_tc128(const float* __restrict__ A,
                            const float* __restrict__ B0, const float* __restrict__ B1,
                            float* __restrict__ C0, float* __restrict__ C1) {
    extern __shared__ float sm[];
    float* As_hi = sm;
    float* As_lo = sm + 4096;
    float* Bs_hi = sm + 8192;
    float* Bs_lo = sm + 8192 + 4352;
    const float* B = blockIdx.z ? B1 : B0;
    float*       C = blockIdx.z ? C1 : C0;
    int tid = threadIdx.x, lane = tid & 31, warp = tid >> 5;
    int m0 = blockIdx.y * 128;
    int m0w = (warp & 3) * 32, n0w = (warp >> 2) * 64;
    float acc[2][8][4] = {};
    for (int k0 = 0; k0 < 128; k0 += 32) {
        if (k0) __syncthreads();
        for (int idx = tid; idx < 1024; idx += 256) {
            int m = idx >> 3, kq = (idx & 7) * 4;
            float4 v = *(const float4*)(A + (size_t)(m0 + m) * 128 + k0 + kq);
            int c = kq ^ ((m & 7) << 2);
            float4 hi, lo;
            split2(v.x, hi.x, lo.x); split2(v.y, hi.y, lo.y);
            split2(v.z, hi.z, lo.z); split2(v.w, hi.w, lo.w);
            *(float4*)(As_hi + m * 32 + c) = hi;
            *(float4*)(As_lo + m * 32 + c) = lo;
        }
        for (int idx = tid; idx < 1024; idx += 256) {
            int k = idx >> 5, nq = (idx & 31) * 4;
            float4 v = *(const float4*)(B + (size_t)(k0 + k) * 128 + nq);
            float4 hi, lo;
            split2(v.x, hi.x, lo.x); split2(v.y, hi.y, lo.y);
            split2(v.z, hi.z, lo.z); split2(v.w, hi.w, lo.w);
            *(float4*)(Bs_hi + k * 136 + nq) = hi;
            *(float4*)(Bs_lo + k * 136 + nq) = lo;
        }
        __syncthreads();
#pragma unroll
        for (int kk = 0; kk < 32; kk += 8) {
            uint32_t ah[2][4], al[2][4];
#pragma unroll
            for (int mt = 0; mt < 2; mt++) {
                int m = m0w + mt * 16 + (lane >> 2);
                int cb = (m & 7) << 2;
                int k_ = kk + (lane & 3);
                ah[mt][0] = __float_as_uint(As_hi[m * 32 + (k_ ^ cb)]);
                ah[mt][1] = __float_as_uint(As_hi[(m + 8) * 32 + (k_ ^ cb)]);
                ah[mt][2] = __float_as_uint(As_hi[m * 32 + ((k_ + 4) ^ cb)]);
                ah[mt][3] = __float_as_uint(As_hi[(m + 8) * 32 + ((k_ + 4) ^ cb)]);
                al[mt][0] = __float_as_uint(As_lo[m * 32 + (k_ ^ cb)]);
                al[mt][1] = __float_as_uint(As_lo[(m + 8) * 32 + (k_ ^ cb)]);
                al[mt][2] = __float_as_uint(As_lo[m * 32 + ((k_ + 4) ^ cb)]);
                al[mt][3] = __float_as_uint(As_lo[(m + 8) * 32 + ((k_ + 4) ^ cb)]);
            }
#pragma unroll
            for (int nt = 0; nt < 8; nt++) {
                int n = n0w + nt * 8 + (lane >> 2);
                int kr = kk + (lane & 3);
                uint32_t bh0 = __float_as_uint(Bs_hi[kr * 136 + n]);
                uint32_t bh1 = __float_as_uint(Bs_hi[(kr + 4) * 136 + n]);
                uint32_t bl0 = __float_as_uint(Bs_lo[kr * 136 + n]);
                uint32_t bl1 = __float_as_uint(Bs_lo[(kr + 4) * 136 + n]);
#pragma unroll
                for (int mt = 0; mt < 2; mt++) {
                    mma8(acc[mt][nt], ah[mt], bh0, bh1);
                    mma8(acc[mt][nt], ah[mt], bl0, bl1);
                    mma8(acc[mt][nt], al[mt], bh0, bh1);
                }
            }
        }
    }
#pragma unroll
    for (int mt = 0; mt < 2; mt++) {
        int row = m0 + m0w + mt * 16 + (lane >> 2);
#pragma unroll
        for (int nt = 0; nt < 8; nt++) {
            int col = n0w + nt * 8 + 2 * (lane & 3);
            *(float2*)(C + (size_t)row * 128 + col) =
                make_float2(acc[mt][nt][0], acc[mt][nt][1]);
            *(float2*)(C + (size_t)(row + 8) * 128 + col) =
                make_float2(acc[mt][nt][2], acc[mt][nt][3]);
        }
    }
}

// ---------------- tf32 split-mma GEMM N=32 (both weights, one pass over A) -------------
__global__ void __launch_bounds__(256) k_gemm_tc32(const float* __restrict__ A,
                            const float* __restrict__ B0, const float* __restrict__ B1,
                            float* __restrict__ C0, float* __restrict__ C1) {
    extern __shared__ float sm[];
    float* As_hi = sm;                 // 4096
    float* As_lo = sm + 4096;          // 4096
    float* Bh0 = sm + 8192;            // 4608 each (128 x 36)
    float* Bl0 = sm + 12800;
    float* Bh1 = sm + 17408;
    float* Bl1 = sm + 22016;
    int tid = threadIdx.x, lane = tid & 31, warp = tid >> 5;
    int m0 = blockIdx.x * 128;
    for (int idx = tid; idx < 4096; idx += 256) {
        int k = idx >> 5, n = idx & 31;
        float h, l;
        split2(B0[idx], h, l); Bh0[k * 36 + n] = h; Bl0[k * 36 + n] = l;
        split2(B1[idx], h, l); Bh1[k * 36 + n] = h; Bl1[k * 36 + n] = l;
    }
    float acc[2][4][4] = {};
    for (int k0 = 0; k0 < 128; k0 += 32) {
        __syncthreads();
        for (int idx = tid; idx < 1024; idx += 256) {
            int m = idx >> 3, kq = (idx & 7) * 4;
            float4 v = *(const float4*)(A + (size_t)(m0 + m) * 128 + k0 + kq);
            int c = kq ^ ((m & 7) << 2);
            float4 hi, lo;
            split2(v.x, hi.x, lo.x); split2(v.y, hi.y, lo.y);
            split2(v.z, hi.z, lo.z); split2(v.w, hi.w, lo.w);
            *(float4*)(As_hi + m * 32 + c) = hi;
            *(float4*)(As_lo + m * 32 + c) = lo;
        }
        __syncthreads();
#pragma unroll
        for (int kk = 0; kk < 32; kk += 8) {
            uint32_t ah[4], al[4];
            int m = warp * 16 + (lane >> 2);
            int cb = (m & 7) << 2;
            int k_ = kk + (lane & 3);
            ah[0] = __float_as_uint(As_hi[m * 32 + (k_ ^ cb)]);
            ah[1] = __float_as_uint(As_hi[(m + 8) * 32 + (k_ ^ cb)]);
            ah[2] = __float_as_uint(As_hi[m * 32 + ((k_ + 4) ^ cb)]);
            ah[3] = __float_as_uint(As_hi[(m + 8) * 32 + ((k_ + 4) ^ cb)]);
            al[0] = __float_as_uint(As_lo[m * 32 + (k_ ^ cb)]);
            al[1] = __float_as_uint(As_lo[(m + 8) * 32 + (k_ ^ cb)]);
            al[2] = __float_as_uint(As_lo[m * 32 + ((k_ + 4) ^ cb)]);
            al[3] = __float_as_uint(As_lo[(m + 8) * 32 + ((k_ + 4) ^ cb)]);
            int kg = k0 + kk + (lane & 3);   // GLOBAL B row
#pragma unroll
            for (int nt = 0; nt < 4; nt++) {
                int n = nt * 8 + (lane >> 2);
                uint32_t bh0 = __float_as_uint(Bh0[kg * 36 + n]);
                uint32_t bh1 = __float_as_uint(Bh0[(kg + 4) * 36 + n]);
                uint32_t bl0 = __float_as_uint(Bl0[kg * 36 + n]);
                uint32_t bl1 = __float_as_uint(Bl0[(kg + 4) * 36 + n]);
                mma8(acc[0][nt], ah, bh0, bh1);
                mma8(acc[0][nt], ah, bl0, bl1);
                mma8(acc[0][nt], al, bh0, bh1);
                uint32_t ch0 = __float_as_uint(Bh1[kg * 36 + n]);
                uint32_t ch1 = __float_as_uint(Bh1[(kg + 4) * 36 + n]);
                uint32_t cl0 = __float_as_uint(Bl1[kg * 36 + n]);
                uint32_t cl1 = __float_as_uint(Bl1[(kg + 4) * 36 + n]);
                mma8(acc[1][nt], ah, ch0, ch1);
                mma8(acc[1][nt], ah, cl0, cl1);
                mma8(acc[1][nt], al, ch0, ch1);
            }
        }
    }
#pragma unroll
    for (int z = 0; z < 2; z++) {
        float* C = z ? C1 : C0;
        int row = m0 + warp * 16 + (lane >> 2);
#pragma unroll
        for (int nt = 0; nt < 4; nt++) {
            int col = nt * 8 + 2 * (lane & 3);
            *(float2*)(C + (size_t)row * 32 + col) =
                make_float2(acc[z][nt][0], acc[z][nt][1]);
            *(float2*)(C + (size_t)(row + 8) * 32 + col) =
                make_float2(acc[z][nt][2], acc[z][nt][3]);
        }
    }
}

// ---------------- aggr layers 0/1: lane=(head,4ch), prefetched edge pipeline ------------
__global__ void __launch_bounds__(256) k_aggr32c(const float* __restrict__ att,
        const float* __restrict__ We, const float* __restrict__ bias,
        const float* __restrict__ xl, const float* __restrict__ xr,
        float* __restrict__ out) {
    int gid  = blockIdx.x * 8 + (threadIdx.x >> 5);
    int lane = threadIdx.x & 31;
    if (gid >= NN * (GNUM / 2)) return;
    int d  = gid / (GNUM / 2);
    int g0 = (gid - d * (GNUM / 2)) * 2;
    int rs = g_rowstart[d], re = g_rowstart[d + 1];
    int off = (lane >> 3) * 32 + (lane & 7) * 4;
    float4 attv = *(const float4*)(att + off);
    float4 we0v = *(const float4*)(We + off);
    float4 we1v = *(const float4*)(We + 128 + off);
    const float* xl0 = xl + (size_t)g0 * NN * 128 + off;
    const float* xl1 = xl + (size_t)(g0 + 1) * NN * 128 + off;
    float4 xrv[2], acc[2];
    float den[2];
#pragma unroll
    for (int q = 0; q < 2; q++) {
        xrv[q] = *(const float4*)(xr + ((size_t)(g0 + q) * NN + d) * 128 + off);
        acc[q] = make_float4(0.f, 0.f, 0.f, 0.f);
        den[q] = 0.f;
    }
    float4 se = make_float4(0.f, 0.f, 0.f, 0.f);
    float4 xc0 = make_float4(0.f, 0.f, 0.f, 0.f), xc1 = xc0;
    if (rs < re) {
        se = g_psea[rs];
        int s = __float_as_int(se.x);
        xc0 = *(const float4*)(xl0 + (size_t)s * 128);
        xc1 = *(const float4*)(xl1 + (size_t)s * 128);
    }
#pragma unroll 2
    for (int i = rs; i < re; i++) {
        int inx = (i + 1 < re) ? i + 1 : i;
        float4 se_n = g_psea[inx];
        int sn = __float_as_int(se_n.x);
        float4 xn0 = *(const float4*)(xl0 + (size_t)sn * 128);
        float4 xn1 = *(const float4*)(xl1 + (size_t)sn * 128);
        float4 ew;
        ew.x = se.y * we0v.x + se.z * we1v.x;
        ew.y = se.y * we0v.y + se.z * we1v.y;
        ew.z = se.y * we0v.z + se.z * we1v.z;
        ew.w = se.y * we0v.w + se.z * we1v.w;
        {
            float v0 = xc0.x + xrv[0].x + ew.x;
            float v1 = xc0.y + xrv[0].y + ew.y;
            float v2 = xc0.z + xrv[0].z + ew.z;
            float v3 = xc0.w + xrv[0].w + ew.w;
            v0 = (v0 > 0.f ? v0 : 0.2f * v0) * attv.x;
            v1 = (v1 > 0.f ? v1 : 0.2f * v1) * attv.y;
            v2 = (v2 > 0.f ? v2 : 0.2f * v2) * attv.z;
            v3 = (v3 > 0.f ? v3 : 0.2f * v3) * attv.w;
            float ssum = (v0 + v1) + (v2 + v3);
            ssum += __shfl_xor_sync(0xffffffffu, ssum, 4);
            ssum += __shfl_xor_sync(0xffffffffu, ssum, 2);
            ssum += __shfl_xor_sync(0xffffffffu, ssum, 1);
            float p = __expf(ssum);
            den[0] += p;
            acc[0].x += p * xc0.x;
            acc[0].y += p * xc0.y;
            acc[0].z += p * xc0.z;
            acc[0].w += p * xc0.w;
        }
        {
            float v0 = xc1.x + xrv[1].x + ew.x;
            float v1 = xc1.y + xrv[1].y + ew.y;
            float v2 = xc1.z + xrv[1].z + ew.z;
            float v3 = xc1.w + xrv[1].w + ew.w;
            v0 = (v0 > 0.f ? v0 : 0.2f * v0) * attv.x;
            v1 = (v1 > 0.f ? v1 : 0.2f * v1) * attv.y;
            v2 = (v2 > 0.f ? v2 : 0.2f * v2) * attv.z;
            v3 = (v3 > 0.f ? v3 : 0.2f * v3) * attv.w;
            float ssum = (v0 + v1) + (v2 + v3);
            ssum += __shfl_xor_sync(0xffffffffu, ssum, 4);
            ssum += __shfl_xor_sync(0xffffffffu, ssum, 2);
            ssum += __shfl_xor_sync(0xffffffffu, ssum, 1);
            float p = __expf(ssum);
            den[1] += p;
            acc[1].x += p * xc1.x;
            acc[1].y += p * xc1.y;
            acc[1].z += p * xc1.z;
            acc[1].w += p * xc1.w;
        }
        se = se_n; xc0 = xn0; xc1 = xn1;
    }
    float4 bv = *(const float4*)(bias + off);
#pragma unroll
    for (int q = 0; q < 2; q++) {
        float inv = 1.f / (den[q] + 1e-16f);
        float4 o;
        o.x = fmaxf(acc[q].x * inv + bv.x, 0.f);
        o.y = fmaxf(acc[q].y * inv + bv.y, 0.f);
        o.z = fmaxf(acc[q].z * inv + bv.z, 0.f);
        o.w = fmaxf(acc[q].w * inv + bv.w, 0.f);
        *(float4*)(out + ((size_t)(g0 + q) * NN + d) * 128 + off) = o;
    }
}

// ---------------- aggr layer 2: canonical layout, 4 graphs/warp, prefetch pipeline ------
__global__ void __launch_bounds__(256) k_aggr8c(const float* __restrict__ att,
        const float* __restrict__ We, const float* __restrict__ bias,
        const float* __restrict__ xl, const float* __restrict__ xr,
        float* __restrict__ out) {
    int gid  = blockIdx.x * 8 + (threadIdx.x >> 5);
    int lane = threadIdx.x & 31;
    if (gid >= NN * (GNUM / 4)) return;
    int d  = gid / (GNUM / 4);
    int g0 = (gid - d * (GNUM / 4)) * 4;
    int rs = g_rowstart[d], re = g_rowstart[d + 1];
    float attv = att[lane], we0v = We[lane], we1v = We[32 + lane];
    const float* xlb[4];
#pragma unroll
    for (int q = 0; q < 4; q++) xlb[q] = xl + (size_t)(g0 + q) * NN * 32 + lane;
    float xrv[4], acc[4] = {}, den[4] = {};
#pragma unroll
    for (int q = 0; q < 4; q++)
        xrv[q] = xr[((size_t)(g0 + q) * NN + d) * 32 + lane];
    float4 se = make_float4(0.f, 0.f, 0.f, 0.f);
    float xc[4] = {};
    if (rs < re) {
        se = g_psea[rs];
        int s = __float_as_int(se.x);
#pragma unroll
        for (int q = 0; q < 4; q++) xc[q] = xlb[q][(size_t)s * 32];
    }
#pragma unroll 2
    for (int i = rs; i < re; i++) {
        int inx = (i + 1 < re) ? i + 1 : i;
        float4 se_n = g_psea[inx];
        int sn = __float_as_int(se_n.x);
        float xn[4];
#pragma unroll
        for (int q = 0; q < 4; q++) xn[q] = xlb[q][(size_t)sn * 32];
        float ew = se.y * we0v + se.z * we1v;
#pragma unroll
        for (int q = 0; q < 4; q++) {
            float v = xc[q] + xrv[q] + ew;
            v = (v > 0.f ? v : 0.2f * v) * attv;
            v += __shfl_xor_sync(0xffffffffu, v, 4);
            v += __shfl_xor_sync(0xffffffffu, v, 2);
            v += __shfl_xor_sync(0xffffffffu, v, 1);
            float p = __expf(v);
            den[q] += p;
            acc[q] += p * xc[q];
        }
        se = se_n;
#pragma unroll
        for (int q = 0; q < 4; q++) xc[q] = xn[q];
    }
    float bv = bias[lane];
#pragma unroll
    for (int q = 0; q < 4; q++)
        out[((size_t)(g0 + q) * NN + d) * 32 + lane] =
            fmaxf(acc[q] / (den[q] + 1e-16f) + bv, 0.f);
}

// ---------------- LSTM input projection (tf32, split-K; wih hi-only) -------------------
// Slot permutation: fragment slot s in each k8 group holds PHYSICAL k = 2*(s&3)+(s>>2).
__global__ void __launch_bounds__(256)
k_gates_tc(const float* __restrict__ emb, const float* __restrict__ wih) {
    extern __shared__ float sm[];
    float* eh = sm;
    float* el = sm + 40 * 260;
    int tid = threadIdx.x, lane = tid & 31, warp = tid >> 5;
    int chunk = blockIdx.x;
    int j0w = blockIdx.y * 512 + warp * 64;
    float acc[4][5][4] = {};
#pragma unroll 1
    for (int sub = 0; sub < 2; sub++) {
        int kbase = chunk * KC + sub * 256;
        if (sub) __syncthreads();
        for (int idx = tid; idx < 40 * 64; idx += 256) {
            int gg = idx >> 6, kq = (idx & 63) * 4;
            float4 v = *(const float4*)(emb + (size_t)gg * 64000 + kbase + kq);
            float hv[4], lv[4];
            split2(v.x, hv[0], lv[0]); split2(v.y, hv[1], lv[1]);
            split2(v.z, hv[2], lv[2]); split2(v.w, hv[3], lv[3]);
            int grp = kq & ~7;
            float* ehp = eh + gg * 260 + grp;
            float* elp = el + gg * 260 + grp;
#pragma unroll
            for (int j = 0; j < 4; j++) {
                int pp = (kq + j) & 7;
                int slot = (pp >> 1) + ((pp & 1) << 2);
                ehp[slot] = hv[j];
                elp[slot] = lv[j];
            }
        }
        __syncthreads();
#pragma unroll 1
        for (int kk = 0; kk < 256; kk += 8) {
            uint32_t ah[4][4];
#pragma unroll
            for (int mt = 0; mt < 4; mt++) {
                const float* ap = wih + (size_t)(j0w + mt * 16 + (lane >> 2)) * 64000
                                + kbase + kk + 2 * (lane & 3);
                float2 r0 = __ldg((const float2*)ap);
                float2 r1 = __ldg((const float2*)(ap + (size_t)8 * 64000));
                ah[mt][0] = f2tf(r0.x);
                ah[mt][1] = f2tf(r1.x);
                ah[mt][2] = f2tf(r0.y);
                ah[mt][3] = f2tf(r1.y);
            }
#pragma unroll
            for (int nt = 0; nt < 5; nt++) {
                int gg = nt * 8 + (lane >> 2);
                int kr = kk + (lane & 3);
                uint32_t bh0 = __float_as_uint(eh[gg * 260 + kr]);
                uint32_t bh1 = __float_as_uint(eh[gg * 260 + kr + 4]);
                uint32_t bl0 = __float_as_uint(el[gg * 260 + kr]);
                uint32_t bl1 = __float_as_uint(el[gg * 260 + kr + 4]);
#pragma unroll
                for (int mt = 0; mt < 4; mt++) {
                    mma8(acc[mt][nt], ah[mt], bh0, bh1);
                    mma8(acc[mt][nt], ah[mt], bl0, bl1);
                }
            }
        }
    }
    float* pbase = g_part + (size_t)chunk * 1024 * GNUM;
#pragma unroll
    for (int mt = 0; mt < 4; mt++) {
        int j = j0w + mt * 16 + (lane >> 2);
#pragma unroll
        for (int nt = 0; nt < 5; nt++) {
            int gg = nt * 8 + 2 * (lane & 3);
            *(float2*)(pbase + (size_t)j * GNUM + gg) =
                make_float2(acc[mt][nt][0], acc[mt][nt][1]);
            *(float2*)(pbase + (size_t)(j + 8) * GNUM + gg) =
                make_float2(acc[mt][nt][2], acc[mt][nt][3]);
        }
    }
}

__global__ void k_gates_reduce(const float* __restrict__ bih, const float* __restrict__ bhh) {
    int i = blockIdx.x * blockDim.x + threadIdx.x;
    if (i >= 1024 * GNUM) return;
    int j = i / GNUM, gi = i - j * GNUM;
    float s = bih[j] + bhh[j];
    for (int c = 0; c < NCHUNK; c++) s += g_part[(size_t)c * 1024 * GNUM + i];
    g_gates[gi * 1024 + j] = s;
}

// ---------------- persistent LSTM: all 10 steps, 8 co-resident blocks ----------------
__device__ __forceinline__ float sigf(float x) { return 1.f / (1.f + __expf(-x)); }
__device__ __forceinline__ float tanhfast(float x) { return 1.f - 2.f / (__expf(2.f * x) + 1.f); }

__global__ void __launch_bounds__(128) k_lstm_all() {
    extern __shared__ float sm[];
    float* sw = sm;            // [256][128] whht slice = 128 KB
    float* hs = sm + 32768;    // [1024]
    float* sc = sm + 33792;    // [1024] per-block replica of c state
    int tid = threadIdx.x;
    int j0 = blockIdx.x * 128;
    for (int k = 0; k < 256; k++)
        sw[k * 128 + tid] = g_whht[k * 1024 + j0 + tid];
    for (int i = tid; i < 1024; i += 128) { sc[i] = 0.f; hs[i] = 0.f; }
    __syncthreads();
    for (int t = 0; t < TT; t++) {
        if (t > 0) {
            for (int idx = tid; idx < 1024; idx += 128) {
                int b = idx >> 8, k = idx & 255;
                const float* ga = g_gacc + b * 1024;
                float iv = __ldcg(ga + k);
                float fv = __ldcg(ga + 256 + k);
                float gv = __ldcg(ga + 512 + k);
                float ov = __ldcg(ga + 768 + k);
                float c = sigf(fv) * sc[idx] + sigf(iv) * tanhfast(gv);
                sc[idx] = c;
                hs[idx] = sigf(ov) * tanhfast(c);
            }
            __syncthreads();
        }
        float acc[BB];
#pragma unroll
        for (int b = 0; b < BB; b++) acc[b] = g_gates[(size_t)(b * TT + t) * 1024 + j0 + tid];
#pragma unroll 8
        for (int k = 0; k < 256; k++) {
            float w = sw[k * 128 + tid];
#pragma unroll
            for (int b = 0; b < BB; b++) acc[b] += w * hs[b * 256 + k];
        }
#pragma unroll
        for (int b = 0; b < BB; b++) __stcg(&g_gacc[b * 1024 + j0 + tid], acc[b]);
        if (t < TT - 1) {
            __threadfence();
            __syncthreads();
            if (tid == 0) {
                atomicAdd(&g_ctr, 1);
                while (atomicAdd(&g_ctr, 0) < 8 * (t + 1)) {}
            }
            __syncthreads();
            __threadfence();
        }
    }
    if (blockIdx.x == 0)
        for (int i = tid; i < 1024; i += 128) g_c8[i] = sc[i];
}

// ---------------- final head ----------------
__global__ void __launch_bounds__(512) k_fc(const float* __restrict__ fc1w,
                     const float* __restrict__ fc1b,
                     const float* __restrict__ fc2w, const float* __restrict__ fc2b,
                     float* __restrict__ out) {
    __shared__ float last[BB * 256];
    __shared__ float hid[BB * 512];
    __shared__ float red[512];
    int j = threadIdx.x;
    for (int idx = j; idx < BB * 256; idx += 512) {
        int b = idx >> 8, k = idx & 255;
        const float* ga = g_gacc + b * 1024;
        float iv = ga[k], fv = ga[256 + k], gv = ga[512 + k], ov = ga[768 + k];
        float c = sigf(fv) * g_c8[idx] + sigf(iv) * tanhfast(gv);
        last[idx] = fmaxf(sigf(ov) * tanhfast(c), 0.f);
    }
    __syncthreads();
    for (int b = 0; b < BB; b++) {
        float acc = fc1b[j];
        for (int k = 0; k < 256; k++) acc += last[b * 256 + k] * fc1w[k * 512 + j];
        hid[b * 512 + j] = fmaxf(acc, 0.f);
    }
    __syncthreads();
    for (int b = 0; b < BB; b++) {
        red[j] = hid[b * 512 + j] * fc2w[j];
        __syncthreads();
        for (int o = 256; o; o >>= 1) {
            if (j < o) red[j] += red[j + o];
            __syncthreads();
        }
        if (j == 0) out[b] = red[0] + fc2b[0];
        __syncthreads();
    }
}

// ---------------- host launcher ----------------
extern "C" void kernel_launch(void* const* d_in, const int* in_sizes, int n_in,
                              void* d_out, int out_size) {
    const float* x    = (const float*)d_in[0];
    const int*   ei   = (const int*)d_in[1];
    const float* ea   = (const float*)d_in[2];
    const float* wl0  = (const float*)d_in[3];
    const float* wr0  = (const float*)d_in[4];
    const float* we0  = (const float*)d_in[5];
    const float* att0 = (const float*)d_in[6];
    const float* b0   = (const float*)d_in[7];
    const float* wl1  = (const float*)d_in[8];
    const float* wr1  = (const float*)d_in[9];
    const float* we1  = (const float*)d_in[10];
    const float* att1 = (const float*)d_in[11];
    const float* b1   = (const float*)d_in[12];
    const float* wl2  = (const float*)d_in[13];
    const float* wr2  = (const float*)d_in[14];
    const float* we2  = (const float*)d_in[15];
    const float* att2 = (const float*)d_in[16];
    const float* b2   = (const float*)d_in[17];
    const float* wih  = (const float*)d_in[18];
    const float* whh  = (const float*)d_in[19];
    const float* bih  = (const float*)d_in[20];
    const float* bhh  = (const float*)d_in[21];
    const float* fc1w = (const float*)d_in[22];
    const float* fc1b = (const float*)d_in[23];
    const float* fc2w = (const float*)d_in[24];
    const float* fc2b = (const float*)d_in[25];

    void *p_xl, *p_xr, *p_hA, *p_hB;
    cudaGetSymbolAddress(&p_xl, g_xl);
    cudaGetSymbolAddress(&p_xr, g_xr);
    cudaGetSymbolAddress(&p_hA, g_hA);
    cudaGetSymbolAddress(&p_hB, g_hB);
    float* xl = (float*)p_xl;
    float* xr = (float*)p_xr;
    float* hA = (float*)p_hA;
    float* hB = (float*)p_hB;

    const int M = GNUM * NN;
    const int SMEM_TC   = (8192 + 8704) * 4;
    const int SMEM_TC32 = 26624 * 4;
    const int SMEM_GATE = 2 * 40 * 260 * 4;
    const int SMEM_LSTM = (32768 + 2048) * 4;
    cudaFuncSetAttribute(k_gemm_tc128, cudaFuncAttributeMaxDynamicSharedMemorySize, SMEM_TC);
    cudaFuncSetAttribute(k_gemm_tc32, cudaFuncAttributeMaxDynamicSharedMemorySize, SMEM_TC32);
    cudaFuncSetAttribute(k_gates_tc, cudaFuncAttributeMaxDynamicSharedMemorySize, SMEM_GATE);
    cudaFuncSetAttribute(k_lstm_all, cudaFuncAttributeMaxDynamicSharedMemorySize, SMEM_LSTM);

    k_prep_all<<<1, 1024>>>(ei, ea);
    k_whht<<<1024, 256>>>(whh);

    // ---- layer 0: 8 -> 128 ----
    k_gemm_n128<<<dim3(1, M / 128, 2), 256>>>(x, wl0, wr0, xl, xr, 8);
    k_aggr32c<<<5000, 256>>>(att0, we0, b0, xl, xr, hA);

    // ---- layer 1: 128 -> 128 (tf32) ----
    k_gemm_tc128<<<dim3(1, M / 128, 2), 256, SMEM_TC>>>(hA, wl1, wr1, xl, xr);
    k_aggr32c<<<5000, 256>>>(att1, we1, b1, xl, xr, hB);

    // ---- layer 2: 128 -> 32 (tf32, both weights in one pass) ----
    k_gemm_tc32<<<M / 128, 256, SMEM_TC32>>>(hB, wl2, wr2, xl, xr);
    k_aggr8c<<<2500, 256>>>(att2, we2, b2, xl, xr, hA);  // hA = emb [40][64000]

    // ---- LSTM input projection ----
    k_gates_tc<<<dim3(NCHUNK, 2), 256, SMEM_GATE>>>(hA, wih);
    k_gates_reduce<<<(1024 * GNUM + 255) / 256, 256>>>(bih, bhh);

    // ---- LSTM (persistent, all 10 steps) + head ----
    k_lstm_all<<<8, 128, SMEM_LSTM>>>();
    k_fc<<<1, 512>>>(fc1w, fc1b, fc2w, fc2b, (float*)d_out);
}

// round 17
// speedup vs baseline: 1.1693x; 1.1693x over previous
#include <cuda_runtime.h>
#include <cstdint>

#define GNUM 40
#define NN   2000
#define E0   16000
#define ET   18000
#define TT   10
#define BB   4
#define KC   512
#define NCHUNK 125

// ---------------- scratch ----------------
__device__ float  g_xl[GNUM * NN * 128];
__device__ float  g_xr[GNUM * NN * 128];
__device__ float  g_hA[GNUM * NN * 128];
__device__ float  g_hB[GNUM * NN * 128];
__device__ int    g_rowstart[NN + 1];
__device__ float4 g_psea[ET];              // (bitcast src, ea.x, ea.y, 0)
__device__ float  g_gates[GNUM * 1024];
__device__ float  g_part[NCHUNK * 1024 * GNUM];
__device__ float  g_gacc[BB * 1024];
__device__ float  g_whht[256 * 1024];
__device__ float  g_c8[BB * 256];
__device__ int    g_ctr;

// ---------------- tf32 helpers ----------------
__device__ __forceinline__ uint32_t f2tf(float v) {
    uint32_t r; asm("cvt.rna.tf32.f32 %0, %1;" : "=r"(r) : "f"(v)); return r;
}
__device__ __forceinline__ void split2(float v, float& hi, float& lo) {
    hi = __uint_as_float(f2tf(v));
    lo = __uint_as_float(f2tf(v - hi));
}
__device__ __forceinline__ void mma8(float (&c)[4], const uint32_t (&a)[4],
                                     uint32_t b0, uint32_t b1) {
    asm volatile(
        "mma.sync.aligned.m16n8k8.row.col.f32.tf32.tf32.f32 "
        "{%0,%1,%2,%3},{%4,%5,%6,%7},{%8,%9},{%0,%1,%2,%3};"
        : "+f"(c[0]), "+f"(c[1]), "+f"(c[2]), "+f"(c[3])
        : "r"(a[0]), "r"(a[1]), "r"(a[2]), "r"(a[3]), "r"(b0), "r"(b1));
}

// ---------------- fused prep (1 block) ----------------
__global__ void __launch_bounds__(1024) k_prep_all(const int* __restrict__ ei,
                                                   const float* __restrict__ ea) {
    __shared__ int   sdeg[NN];
    __shared__ int   sscan[1024];
    __shared__ float r0[1024], r1[1024];
    __shared__ float2 smean;
    int t = threadIdx.x;
    float a = 0.f, b = 0.f;
    for (int e = t; e < E0; e += 1024) { a += ea[2 * e]; b += ea[2 * e + 1]; }
    r0[t] = a; r1[t] = b;
    for (int i = t; i < NN; i += 1024) sdeg[i] = 0;
    __syncthreads();
    for (int o = 512; o; o >>= 1) {
        if (t < o) { r0[t] += r0[t + o]; r1[t] += r1[t + o]; }
        __syncthreads();
    }
    if (t == 0) { smean.x = r0[0] / E0; smean.y = r1[0] / E0; }
    for (int e = t; e < ET; e += 1024) {
        int d = (e < E0) ? ei[E0 + e] : (e - E0);
        atomicAdd(&sdeg[d], 1);
    }
    __syncthreads();
    int i0 = 2 * t, i1 = 2 * t + 1;
    int v0 = (i0 < NN) ? sdeg[i0] : 0;
    int v1 = (i1 < NN) ? sdeg[i1] : 0;
    int tot = v0 + v1;
    sscan[t] = tot;
    __syncthreads();
    for (int off = 1; off < 1024; off <<= 1) {
        int x = (t >= off) ? sscan[t - off] : 0;
        __syncthreads();
        sscan[t] += x;
        __syncthreads();
    }
    int base = sscan[t] - tot;
    __syncthreads();
    if (i0 < NN) { g_rowstart[i0] = base;      sdeg[i0] = base; }
    if (i1 < NN) { g_rowstart[i1] = base + v0; sdeg[i1] = base + v0; }
    if (t == 1023) g_rowstart[NN] = sscan[1023];
    __syncthreads();
    float2 mn = smean;
    for (int e = t; e < ET; e += 1024) {
        int s, d;
        if (e < E0) { s = ei[e]; d = ei[E0 + e]; }
        else        { s = d = e - E0; }
        int pos = atomicAdd(&sdeg[d], 1);
        float2 v;
        if (e < E0) { v.x = ea[2 * e]; v.y = ea[2 * e + 1]; }
        else        v = mn;
        g_psea[pos] = make_float4(__int_as_float(s), v.x, v.y, 0.f);
    }
}

// ---------------- whh transpose + barrier counter reset ----------------
__global__ void k_whht(const float* __restrict__ whh) {
    int i = blockIdx.x * 256 + threadIdx.x;
    int j = i >> 8, k = i & 255;
    g_whht[k * 1024 + j] = whh[i];
    if (i == 0) g_ctr = 0;
}

// ---------------- fp32 GEMM N=128 (layer 0, K=8) ----------------
__global__ void __launch_bounds__(256) k_gemm_n128(const float* __restrict__ A,
                            const float* __restrict__ B0, const float* __restrict__ B1,
                            float* __restrict__ C0, float* __restrict__ C1, int K) {
    const float* B = blockIdx.z ? B1 : B0;
    float*       C = blockIdx.z ? C1 : C0;
    __shared__ float As[8][128];
    __shared__ float Bs[8][128];
    int tid = threadIdx.x;
    int m0 = blockIdx.y * 128;
    int arow = tid >> 1, acol4 = (tid & 1) * 4;
    int brow = tid >> 5, bcol = (tid & 31) * 4;
    int tx = tid & 15, ty = tid >> 4;
    const float* Ap = A + (size_t)(m0 + arow) * K + acol4;
    float4 av = *(const float4*)Ap;
    float4 bv = *(const float4*)(B + (size_t)brow * 128 + bcol);
    float acc[8][8] = {};
    for (int k0 = 0; k0 < K; k0 += 8) {
        As[acol4 + 0][arow] = av.x; As[acol4 + 1][arow] = av.y;
        As[acol4 + 2][arow] = av.z; As[acol4 + 3][arow] = av.w;
        *(float4*)&Bs[brow][bcol] = bv;
        __syncthreads();
        if (k0 + 8 < K) {
            av = *(const float4*)(Ap + k0 + 8);
            bv = *(const float4*)(B + (size_t)(k0 + 8 + brow) * 128 + bcol);
        }
#pragma unroll
        for (int kk = 0; kk < 8; kk++) {
            float a[8], b[8];
            *(float4*)a       = *(const float4*)&As[kk][ty * 8];
            *(float4*)(a + 4) = *(const float4*)&As[kk][ty * 8 + 4];
            *(float4*)b       = *(const float4*)&Bs[kk][tx * 8];
            *(float4*)(b + 4) = *(const float4*)&Bs[kk][tx * 8 + 4];
#pragma unroll
            for (int i = 0; i < 8; i++)
#pragma unroll
                for (int j = 0; j < 8; j++) acc[i][j] += a[i] * b[j];
        }
        __syncthreads();
    }
#pragma unroll
    for (int i = 0; i < 8; i++) {
        float* cp = C + (size_t)(m0 + ty * 8 + i) * 128 + tx * 8;
        *(float4*)cp       = *(float4*)&acc[i][0];
        *(float4*)(cp + 4) = *(float4*)&acc[i][4];
    }
}

// ---------------- tf32 split-mma GEMM N=128 (2-term: ah*bh + ah*bl) ----------------
__global__ void __launch_bounds__(256) k_gemm_tc128(const float* __restrict__ A,
                            const float* __restrict__ B0, const float* __restrict__ B1,
                            float* __restrict__ C0, float* __restrict__ C1) {
    extern __shared__ float sm[];
    float* As_hi = sm;                 // 4096
    float* Bs_hi = sm + 4096;          // 4352
    float* Bs_lo = sm + 4096 + 4352;   // 4352
    const float* B = blockIdx.z ? B1 : B0;
    float*       C = blockIdx.z ? C1 : C0;
    int tid = threadIdx.x, lane = tid & 31, warp = tid >> 5;
    int m0 = blockIdx.y * 128;
    int m0w = (warp & 3) * 32, n0w = (warp >> 2) * 64;
    float acc[2][8][4] = {};
    for (int k0 = 0; k0 < 128; k0 += 32) {
        if (k0) __syncthreads();
        for (int idx = tid; idx < 1024; idx += 256) {
            int m = idx >> 3, kq = (idx & 7) * 4;
            float4 v = *(const float4*)(A + (size_t)(m0 + m) * 128 + k0 + kq);
            int c = kq ^ ((m & 7) << 2);
            float4 hi;
            hi.x = __uint_as_float(f2tf(v.x));
            hi.y = __uint_as_float(f2tf(v.y));
            hi.z = __uint_as_float(f2tf(v.z));
            hi.w = __uint_as_float(f2tf(v.w));
            *(float4*)(As_hi + m * 32 + c) = hi;
        }
        for (int idx = tid; idx < 1024; idx += 256) {
            int k = idx >> 5, nq = (idx & 31) * 4;
            float4 v = *(const float4*)(B + (size_t)(k0 + k) * 128 + nq);
            float4 hi, lo;
            split2(v.x, hi.x, lo.x); split2(v.y, hi.y, lo.y);
            split2(v.z, hi.z, lo.z); split2(v.w, hi.w, lo.w);
            *(float4*)(Bs_hi + k * 136 + nq) = hi;
            *(float4*)(Bs_lo + k * 136 + nq) = lo;
        }
        __syncthreads();
#pragma unroll
        for (int kk = 0; kk < 32; kk += 8) {
            uint32_t ah[2][4];
#pragma unroll
            for (int mt = 0; mt < 2; mt++) {
                int m = m0w + mt * 16 + (lane >> 2);
                int cb = (m & 7) << 2;
                int k_ = kk + (lane & 3);
                ah[mt][0] = __float_as_uint(As_hi[m * 32 + (k_ ^ cb)]);
                ah[mt][1] = __float_as_uint(As_hi[(m + 8) * 32 + (k_ ^ cb)]);
                ah[mt][2] = __float_as_uint(As_hi[m * 32 + ((k_ + 4) ^ cb)]);
                ah[mt][3] = __float_as_uint(As_hi[(m + 8) * 32 + ((k_ + 4) ^ cb)]);
            }
#pragma unroll
            for (int nt = 0; nt < 8; nt++) {
                int n = n0w + nt * 8 + (lane >> 2);
                int kr = kk + (lane & 3);
                uint32_t bh0 = __float_as_uint(Bs_hi[kr * 136 + n]);
                uint32_t bh1 = __float_as_uint(Bs_hi[(kr + 4) * 136 + n]);
                uint32_t bl0 = __float_as_uint(Bs_lo[kr * 136 + n]);
                uint32_t bl1 = __float_as_uint(Bs_lo[(kr + 4) * 136 + n]);
#pragma unroll
                for (int mt = 0; mt < 2; mt++) {
                    mma8(acc[mt][nt], ah[mt], bh0, bh1);
                    mma8(acc[mt][nt], ah[mt], bl0, bl1);
                }
            }
        }
    }
#pragma unroll
    for (int mt = 0; mt < 2; mt++) {
        int row = m0 + m0w + mt * 16 + (lane >> 2);
#pragma unroll
        for (int nt = 0; nt < 8; nt++) {
            int col = n0w + nt * 8 + 2 * (lane & 3);
            *(float2*)(C + (size_t)row * 128 + col) =
                make_float2(acc[mt][nt][0], acc[mt][nt][1]);
            *(float2*)(C + (size_t)(row + 8) * 128 + col) =
                make_float2(acc[mt][nt][2], acc[mt][nt][3]);
        }
    }
}

// ---------------- tf32 split-mma GEMM N=32 (2-term; both weights, one pass over A) -----
__global__ void __launch_bounds__(256) k_gemm_tc32(const float* __restrict__ A,
                            const float* __restrict__ B0, const float* __restrict__ B1,
                            float* __restrict__ C0, float* __restrict__ C1) {
    extern __shared__ float sm[];
    float* As_hi = sm;                 // 4096
    float* Bh0 = sm + 4096;            // 4608 each (128 x 36)
    float* Bl0 = sm + 8704;
    float* Bh1 = sm + 13312;
    float* Bl1 = sm + 17920;
    int tid = threadIdx.x, lane = tid & 31, warp = tid >> 5;
    int m0 = blockIdx.x * 128;
    for (int idx = tid; idx < 4096; idx += 256) {
        int k = idx >> 5, n = idx & 31;
        float h, l;
        split2(B0[idx], h, l); Bh0[k * 36 + n] = h; Bl0[k * 36 + n] = l;
        split2(B1[idx], h, l); Bh1[k * 36 + n] = h; Bl1[k * 36 + n] = l;
    }
    float acc[2][4][4] = {};
    for (int k0 = 0; k0 < 128; k0 += 32) {
        __syncthreads();
        for (int idx = tid; idx < 1024; idx += 256) {
            int m = idx >> 3, kq = (idx & 7) * 4;
            float4 v = *(const float4*)(A + (size_t)(m0 + m) * 128 + k0 + kq);
            int c = kq ^ ((m & 7) << 2);
            float4 hi;
            hi.x = __uint_as_float(f2tf(v.x));
            hi.y = __uint_as_float(f2tf(v.y));
            hi.z = __uint_as_float(f2tf(v.z));
            hi.w = __uint_as_float(f2tf(v.w));
            *(float4*)(As_hi + m * 32 + c) = hi;
        }
        __syncthreads();
#pragma unroll
        for (int kk = 0; kk < 32; kk += 8) {
            uint32_t ah[4];
            int m = warp * 16 + (lane >> 2);
            int cb = (m & 7) << 2;
            int k_ = kk + (lane & 3);
            ah[0] = __float_as_uint(As_hi[m * 32 + (k_ ^ cb)]);
            ah[1] = __float_as_uint(As_hi[(m + 8) * 32 + (k_ ^ cb)]);
            ah[2] = __float_as_uint(As_hi[m * 32 + ((k_ + 4) ^ cb)]);
            ah[3] = __float_as_uint(As_hi[(m + 8) * 32 + ((k_ + 4) ^ cb)]);
            int kg = k0 + kk + (lane & 3);   // GLOBAL B row
#pragma unroll
            for (int nt = 0; nt < 4; nt++) {
                int n = nt * 8 + (lane >> 2);
                uint32_t bh0 = __float_as_uint(Bh0[kg * 36 + n]);
                uint32_t bh1 = __float_as_uint(Bh0[(kg + 4) * 36 + n]);
                uint32_t bl0 = __float_as_uint(Bl0[kg * 36 + n]);
                uint32_t bl1 = __float_as_uint(Bl0[(kg + 4) * 36 + n]);
                mma8(acc[0][nt], ah, bh0, bh1);
                mma8(acc[0][nt], ah, bl0, bl1);
                uint32_t ch0 = __float_as_uint(Bh1[kg * 36 + n]);
                uint32_t ch1 = __float_as_uint(Bh1[(kg + 4) * 36 + n]);
                uint32_t cl0 = __float_as_uint(Bl1[kg * 36 + n]);
                uint32_t cl1 = __float_as_uint(Bl1[(kg + 4) * 36 + n]);
                mma8(acc[1][nt], ah, ch0, ch1);
                mma8(acc[1][nt], ah, cl0, cl1);
            }
        }
    }
#pragma unroll
    for (int z = 0; z < 2; z++) {
        float* C = z ? C1 : C0;
        int row = m0 + warp * 16 + (lane >> 2);
#pragma unroll
        for (int nt = 0; nt < 4; nt++) {
            int col = nt * 8 + 2 * (lane & 3);
            *(float2*)(C + (size_t)row * 32 + col) =
                make_float2(acc[z][nt][0], acc[z][nt][1]);
            *(float2*)(C + (size_t)(row + 8) * 32 + col) =
                make_float2(acc[z][nt][2], acc[z][nt][3]);
        }
    }
}

// ---------------- aggr layers 0/1: lane=(head,4ch), prefetched edge pipeline ------------
__global__ void __launch_bounds__(256) k_aggr32c(const float* __restrict__ att,
        const float* __restrict__ We, const float* __restrict__ bias,
        const float* __restrict__ xl, const float* __restrict__ xr,
        float* __restrict__ out) {
    int gid  = blockIdx.x * 8 + (threadIdx.x >> 5);
    int lane = threadIdx.x & 31;
    if (gid >= NN * (GNUM / 2)) return;
    int d  = gid / (GNUM / 2);
    int g0 = (gid - d * (GNUM / 2)) * 2;
    int rs = g_rowstart[d], re = g_rowstart[d + 1];
    int off = (lane >> 3) * 32 + (lane & 7) * 4;
    float4 attv = *(const float4*)(att + off);
    float4 we0v = *(const float4*)(We + off);
    float4 we1v = *(const float4*)(We + 128 + off);
    const float* xl0 = xl + (size_t)g0 * NN * 128 + off;
    const float* xl1 = xl + (size_t)(g0 + 1) * NN * 128 + off;
    float4 xrv[2], acc[2];
    float den[2];
#pragma unroll
    for (int q = 0; q < 2; q++) {
        xrv[q] = *(const float4*)(xr + ((size_t)(g0 + q) * NN + d) * 128 + off);
        acc[q] = make_float4(0.f, 0.f, 0.f, 0.f);
        den[q] = 0.f;
    }
    float4 se = make_float4(0.f, 0.f, 0.f, 0.f);
    float4 xc0 = make_float4(0.f, 0.f, 0.f, 0.f), xc1 = xc0;
    if (rs < re) {
        se = g_psea[rs];
        int s = __float_as_int(se.x);
        xc0 = *(const float4*)(xl0 + (size_t)s * 128);
        xc1 = *(const float4*)(xl1 + (size_t)s * 128);
    }
#pragma unroll 2
    for (int i = rs; i < re; i++) {
        int inx = (i + 1 < re) ? i + 1 : i;
        float4 se_n = g_psea[inx];
        int sn = __float_as_int(se_n.x);
        float4 xn0 = *(const float4*)(xl0 + (size_t)sn * 128);
        float4 xn1 = *(const float4*)(xl1 + (size_t)sn * 128);
        float4 ew;
        ew.x = se.y * we0v.x + se.z * we1v.x;
        ew.y = se.y * we0v.y + se.z * we1v.y;
        ew.z = se.y * we0v.z + se.z * we1v.z;
        ew.w = se.y * we0v.w + se.z * we1v.w;
        {
            float v0 = xc0.x + xrv[0].x + ew.x;
            float v1 = xc0.y + xrv[0].y + ew.y;
            float v2 = xc0.z + xrv[0].z + ew.z;
            float v3 = xc0.w + xrv[0].w + ew.w;
            v0 = (v0 > 0.f ? v0 : 0.2f * v0) * attv.x;
            v1 = (v1 > 0.f ? v1 : 0.2f * v1) * attv.y;
            v2 = (v2 > 0.f ? v2 : 0.2f * v2) * attv.z;
            v3 = (v3 > 0.f ? v3 : 0.2f * v3) * attv.w;
            float ssum = (v0 + v1) + (v2 + v3);
            ssum += __shfl_xor_sync(0xffffffffu, ssum, 4);
            ssum += __shfl_xor_sync(0xffffffffu, ssum, 2);
            ssum += __shfl_xor_sync(0xffffffffu, ssum, 1);
            float p = __expf(ssum);
            den[0] += p;
            acc[0].x += p * xc0.x;
            acc[0].y += p * xc0.y;
            acc[0].z += p * xc0.z;
            acc[0].w += p * xc0.w;
        }
        {
            float v0 = xc1.x + xrv[1].x + ew.x;
            float v1 = xc1.y + xrv[1].y + ew.y;
            float v2 = xc1.z + xrv[1].z + ew.z;
            float v3 = xc1.w + xrv[1].w + ew.w;
            v0 = (v0 > 0.f ? v0 : 0.2f * v0) * attv.x;
            v1 = (v1 > 0.f ? v1 : 0.2f * v1) * attv.y;
            v2 = (v2 > 0.f ? v2 : 0.2f * v2) * attv.z;
            v3 = (v3 > 0.f ? v3 : 0.2f * v3) * attv.w;
            float ssum = (v0 + v1) + (v2 + v3);
            ssum += __shfl_xor_sync(0xffffffffu, ssum, 4);
            ssum += __shfl_xor_sync(0xffffffffu, ssum, 2);
            ssum += __shfl_xor_sync(0xffffffffu, ssum, 1);
            float p = __expf(ssum);
            den[1] += p;
            acc[1].x += p * xc1.x;
            acc[1].y += p * xc1.y;
            acc[1].z += p * xc1.z;
            acc[1].w += p * xc1.w;
        }
        se = se_n; xc0 = xn0; xc1 = xn1;
    }
    float4 bv = *(const float4*)(bias + off);
#pragma unroll
    for (int q = 0; q < 2; q++) {
        float inv = 1.f / (den[q] + 1e-16f);
        float4 o;
        o.x = fmaxf(acc[q].x * inv + bv.x, 0.f);
        o.y = fmaxf(acc[q].y * inv + bv.y, 0.f);
        o.z = fmaxf(acc[q].z * inv + bv.z, 0.f);
        o.w = fmaxf(acc[q].w * inv + bv.w, 0.f);
        *(float4*)(out + ((size_t)(g0 + q) * NN + d) * 128 + off) = o;
    }
}

// ---------------- aggr layer 2: canonical layout, 4 graphs/warp, prefetch pipeline ------
__global__ void __launch_bounds__(256) k_aggr8c(const float* __restrict__ att,
        const float* __restrict__ We, const float* __restrict__ bias,
        const float* __restrict__ xl, const float* __restrict__ xr,
        float* __restrict__ out) {
    int gid  = blockIdx.x * 8 + (threadIdx.x >> 5);
    int lane = threadIdx.x & 31;
    if (gid >= NN * (GNUM / 4)) return;
    int d  = gid / (GNUM / 4);
    int g0 = (gid - d * (GNUM / 4)) * 4;
    int rs = g_rowstart[d], re = g_rowstart[d + 1];
    float attv = att[lane], we0v = We[lane], we1v = We[32 + lane];
    const float* xlb[4];
#pragma unroll
    for (int q = 0; q < 4; q++) xlb[q] = xl + (size_t)(g0 + q) * NN * 32 + lane;
    float xrv[4], acc[4] = {}, den[4] = {};
#pragma unroll
    for (int q = 0; q < 4; q++)
        xrv[q] = xr[((size_t)(g0 + q) * NN + d) * 32 + lane];
    float4 se = make_float4(0.f, 0.f, 0.f, 0.f);
    float xc[4] = {};
    if (rs < re) {
        se = g_psea[rs];
        int s = __float_as_int(se.x);
#pragma unroll
        for (int q = 0; q < 4; q++) xc[q] = xlb[q][(size_t)s * 32];
    }
#pragma unroll 2
    for (int i = rs; i < re; i++) {
        int inx = (i + 1 < re) ? i + 1 : i;
        float4 se_n = g_psea[inx];
        int sn = __float_as_int(se_n.x);
        float xn[4];
#pragma unroll
        for (int q = 0; q < 4; q++) xn[q] = xlb[q][(size_t)sn * 32];
        float ew = se.y * we0v + se.z * we1v;
#pragma unroll
        for (int q = 0; q < 4; q++) {
            float v = xc[q] + xrv[q] + ew;
            v = (v > 0.f ? v : 0.2f * v) * attv;
            v += __shfl_xor_sync(0xffffffffu, v, 4);
            v += __shfl_xor_sync(0xffffffffu, v, 2);
            v += __shfl_xor_sync(0xffffffffu, v, 1);
            float p = __expf(v);
            den[q] += p;
            acc[q] += p * xc[q];
        }
        se = se_n;
#pragma unroll
        for (int q = 0; q < 4; q++) xc[q] = xn[q];
    }
    float bv = bias[lane];
#pragma unroll
    for (int q = 0; q < 4; q++)
        out[((size_t)(g0 + q) * NN + d) * 32 + lane] =
            fmaxf(acc[q] / (den[q] + 1e-16f) + bv, 0.f);
}

// ---------------- LSTM input projection (tf32, split-K; wih hi-only) -------------------
// Slot permutation: fragment slot s in each k8 group holds PHYSICAL k = 2*(s&3)+(s>>2).
__global__ void __launch_bounds__(256)
k_gates_tc(const float* __restrict__ emb, const float* __restrict__ wih) {
    extern __shared__ float sm[];
    float* eh = sm;
    float* el = sm + 40 * 260;
    int tid = threadIdx.x, lane = tid & 31, warp = tid >> 5;
    int chunk = blockIdx.x;
    int j0w = blockIdx.y * 512 + warp * 64;
    float acc[4][5][4] = {};
#pragma unroll 1
    for (int sub = 0; sub < 2; sub++) {
        int kbase = chunk * KC + sub * 256;
        if (sub) __syncthreads();
        for (int idx = tid; idx < 40 * 64; idx += 256) {
            int gg = idx >> 6, kq = (idx & 63) * 4;
            float4 v = *(const float4*)(emb + (size_t)gg * 64000 + kbase + kq);
            float hv[4], lv[4];
            split2(v.x, hv[0], lv[0]); split2(v.y, hv[1], lv[1]);
            split2(v.z, hv[2], lv[2]); split2(v.w, hv[3], lv[3]);
            int grp = kq & ~7;
            float* ehp = eh + gg * 260 + grp;
            float* elp = el + gg * 260 + grp;
#pragma unroll
            for (int j = 0; j < 4; j++) {
                int pp = (kq + j) & 7;
                int slot = (pp >> 1) + ((pp & 1) << 2);
                ehp[slot] = hv[j];
                elp[slot] = lv[j];
            }
        }
        __syncthreads();
#pragma unroll 1
        for (int kk = 0; kk < 256; kk += 8) {
            uint32_t ah[4][4];
#pragma unroll
            for (int mt = 0; mt < 4; mt++) {
                const float* ap = wih + (size_t)(j0w + mt * 16 + (lane >> 2)) * 64000
                                + kbase + kk + 2 * (lane & 3);
                float2 r0 = __ldg((const float2*)ap);
                float2 r1 = __ldg((const float2*)(ap + (size_t)8 * 64000));
                ah[mt][0] = f2tf(r0.x);
                ah[mt][1] = f2tf(r1.x);
                ah[mt][2] = f2tf(r0.y);
                ah[mt][3] = f2tf(r1.y);
            }
#pragma unroll
            for (int nt = 0; nt < 5; nt++) {
                int gg = nt * 8 + (lane >> 2);
                int kr = kk + (lane & 3);
                uint32_t bh0 = __float_as_uint(eh[gg * 260 + kr]);
                uint32_t bh1 = __float_as_uint(eh[gg * 260 + kr + 4]);
                uint32_t bl0 = __float_as_uint(el[gg * 260 + kr]);
                uint32_t bl1 = __float_as_uint(el[gg * 260 + kr + 4]);
#pragma unroll
                for (int mt = 0; mt < 4; mt++) {
                    mma8(acc[mt][nt], ah[mt], bh0, bh1);
                    mma8(acc[mt][nt], ah[mt], bl0, bl1);
                }
            }
        }
    }
    float* pbase = g_part + (size_t)chunk * 1024 * GNUM;
#pragma unroll
    for (int mt = 0; mt < 4; mt++) {
        int j = j0w + mt * 16 + (lane >> 2);
#pragma unroll
        for (int nt = 0; nt < 5; nt++) {
            int gg = nt * 8 + 2 * (lane & 3);
            *(float2*)(pbase + (size_t)j * GNUM + gg) =
                make_float2(acc[mt][nt][0], acc[mt][nt][1]);
            *(float2*)(pbase + (size_t)(j + 8) * GNUM + gg) =
                make_float2(acc[mt][nt][2], acc[mt][nt][3]);
        }
    }
}

__global__ void k_gates_reduce(const float* __restrict__ bih, const float* __restrict__ bhh) {
    int i = blockIdx.x * blockDim.x + threadIdx.x;
    if (i >= 1024 * GNUM) return;
    int j = i / GNUM, gi = i - j * GNUM;
    float s = bih[j] + bhh[j];
    for (int c = 0; c < NCHUNK; c++) s += g_part[(size_t)c * 1024 * GNUM + i];
    g_gates[gi * 1024 + j] = s;
}

// ---------------- persistent LSTM: all 10 steps, 8 co-resident blocks ----------------
__device__ __forceinline__ float sigf(float x) { return 1.f / (1.f + __expf(-x)); }
__device__ __forceinline__ float tanhfast(float x) { return 1.f - 2.f / (__expf(2.f * x) + 1.f); }

__global__ void __launch_bounds__(128) k_lstm_all() {
    extern __shared__ float sm[];
    float* sw = sm;            // [256][128] whht slice = 128 KB
    float* hs = sm + 32768;    // [1024]
    float* sc = sm + 33792;    // [1024] per-block replica of c state
    int tid = threadIdx.x;
    int j0 = blockIdx.x * 128;
    for (int k = 0; k < 256; k++)
        sw[k * 128 + tid] = g_whht[k * 1024 + j0 + tid];
    for (int i = tid; i < 1024; i += 128) { sc[i] = 0.f; hs[i] = 0.f; }
    __syncthreads();
    for (int t = 0; t < TT; t++) {
        if (t > 0) {
            for (int idx = tid; idx < 1024; idx += 128) {
                int b = idx >> 8, k = idx & 255;
                const float* ga = g_gacc + b * 1024;
                float iv = __ldcg(ga + k);
                float fv = __ldcg(ga + 256 + k);
                float gv = __ldcg(ga + 512 + k);
                float ov = __ldcg(ga + 768 + k);
                float c = sigf(fv) * sc[idx] + sigf(iv) * tanhfast(gv);
                sc[idx] = c;
                hs[idx] = sigf(ov) * tanhfast(c);
            }
            __syncthreads();
        }
        float acc[BB];
#pragma unroll
        for (int b = 0; b < BB; b++) acc[b] = g_gates[(size_t)(b * TT + t) * 1024 + j0 + tid];
#pragma unroll 8
        for (int k = 0; k < 256; k++) {
            float w = sw[k * 128 + tid];
#pragma unroll
            for (int b = 0; b < BB; b++) acc[b] += w * hs[b * 256 + k];
        }
#pragma unroll
        for (int b = 0; b < BB; b++) __stcg(&g_gacc[b * 1024 + j0 + tid], acc[b]);
        if (t < TT - 1) {
            __threadfence();
            __syncthreads();
            if (tid == 0) {
                atomicAdd(&g_ctr, 1);
                while (atomicAdd(&g_ctr, 0) < 8 * (t + 1)) {}
            }
            __syncthreads();
            __threadfence();
        }
    }
    if (blockIdx.x == 0)
        for (int i = tid; i < 1024; i += 128) g_c8[i] = sc[i];
}

// ---------------- final head ----------------
__global__ void __launch_bounds__(512) k_fc(const float* __restrict__ fc1w,
                     const float* __restrict__ fc1b,
                     const float* __restrict__ fc2w, const float* __restrict__ fc2b,
                     float* __restrict__ out) {
    __shared__ float last[BB * 256];
    __shared__ float hid[BB * 512];
    __shared__ float red[512];
    int j = threadIdx.x;
    for (int idx = j; idx < BB * 256; idx += 512) {
        int b = idx >> 8, k = idx & 255;
        const float* ga = g_gacc + b * 1024;
        float iv = ga[k], fv = ga[256 + k], gv = ga[512 + k], ov = ga[768 + k];
        float c = sigf(fv) * g_c8[idx] + sigf(iv) * tanhfast(gv);
        last[idx] = fmaxf(sigf(ov) * tanhfast(c), 0.f);
    }
    __syncthreads();
    for (int b = 0; b < BB; b++) {
        float acc = fc1b[j];
        for (int k = 0; k < 256; k++) acc += last[b * 256 + k] * fc1w[k * 512 + j];
        hid[b * 512 + j] = fmaxf(acc, 0.f);
    }
    __syncthreads();
    for (int b = 0; b < BB; b++) {
        red[j] = hid[b * 512 + j] * fc2w[j];
        __syncthreads();
        for (int o = 256; o; o >>= 1) {
            if (j < o) red[j] += red[j + o];
            __syncthreads();
        }
        if (j == 0) out[b] = red[0] + fc2b[0];
        __syncthreads();
    }
}

// ---------------- host launcher ----------------
extern "C" void kernel_launch(void* const* d_in, const int* in_sizes, int n_in,
                              void* d_out, int out_size) {
    const float* x    = (const float*)d_in[0];
    const int*   ei   = (const int*)d_in[1];
    const float* ea   = (const float*)d_in[2];
    const float* wl0  = (const float*)d_in[3];
    const float* wr0  = (const float*)d_in[4];
    const float* we0  = (const float*)d_in[5];
    const float* att0 = (const float*)d_in[6];
    const float* b0   = (const float*)d_in[7];
    const float* wl1  = (const float*)d_in[8];
    const float* wr1  = (const float*)d_in[9];
    const float* we1  = (const float*)d_in[10];
    const float* att1 = (const float*)d_in[11];
    const float* b1   = (const float*)d_in[12];
    const float* wl2  = (const float*)d_in[13];
    const float* wr2  = (const float*)d_in[14];
    const float* we2  = (const float*)d_in[15];
    const float* att2 = (const float*)d_in[16];
    const float* b2   = (const float*)d_in[17];
    const float* wih  = (const float*)d_in[18];
    const float* whh  = (const float*)d_in[19];
    const float* bih  = (const float*)d_in[20];
    const float* bhh  = (const float*)d_in[21];
    const float* fc1w = (const float*)d_in[22];
    const float* fc1b = (const float*)d_in[23];
    const float* fc2w = (const float*)d_in[24];
    const float* fc2b = (const float*)d_in[25];

    void *p_xl, *p_xr, *p_hA, *p_hB;
    cudaGetSymbolAddress(&p_xl, g_xl);
    cudaGetSymbolAddress(&p_xr, g_xr);
    cudaGetSymbolAddress(&p_hA, g_hA);
    cudaGetSymbolAddress(&p_hB, g_hB);
    float* xl = (float*)p_xl;
    float* xr = (float*)p_xr;
    float* hA = (float*)p_hA;
    float* hB = (float*)p_hB;

    const int M = GNUM * NN;
    const int SMEM_TC   = (4096 + 8704) * 4;          // 51200
    const int SMEM_TC32 = (4096 + 4 * 4608) * 4;      // 90112
    const int SMEM_GATE = 2 * 40 * 260 * 4;
    const int SMEM_LSTM = (32768 + 2048) * 4;
    cudaFuncSetAttribute(k_gemm_tc128, cudaFuncAttributeMaxDynamicSharedMemorySize, SMEM_TC);
    cudaFuncSetAttribute(k_gemm_tc32, cudaFuncAttributeMaxDynamicSharedMemorySize, SMEM_TC32);
    cudaFuncSetAttribute(k_gates_tc, cudaFuncAttributeMaxDynamicSharedMemorySize, SMEM_GATE);
    cudaFuncSetAttribute(k_lstm_all, cudaFuncAttributeMaxDynamicSharedMemorySize, SMEM_LSTM);

    // fork-join: prep + whht on side stream, layer-0 GEMM on main stream
    static cudaStream_t s2 = nullptr;
    static cudaEvent_t evF = nullptr, evJ = nullptr;
    if (!s2) {
        cudaStreamCreateWithFlags(&s2, cudaStreamNonBlocking);
        cudaEventCreateWithFlags(&evF, cudaEventDisableTiming);
        cudaEventCreateWithFlags(&evJ, cudaEventDisableTiming);
    }
    cudaEventRecord(evF, 0);
    cudaStreamWaitEvent(s2, evF, 0);
    k_prep_all<<<1, 1024, 0, s2>>>(ei, ea);
    k_whht<<<1024, 256, 0, s2>>>(whh);
    cudaEventRecord(evJ, s2);

    // ---- layer 0 GEMM: 8 -> 128 (independent of prep) ----
    k_gemm_n128<<<dim3(1, M / 128, 2), 256>>>(x, wl0, wr0, xl, xr, 8);
    cudaStreamWaitEvent(0, evJ, 0);
    k_aggr32c<<<5000, 256>>>(att0, we0, b0, xl, xr, hA);

    // ---- layer 1: 128 -> 128 (tf32, 2-term) ----
    k_gemm_tc128<<<dim3(1, M / 128, 2), 256, SMEM_TC>>>(hA, wl1, wr1, xl, xr);
    k_aggr32c<<<5000, 256>>>(att1, we1, b1, xl, xr, hB);

    // ---- layer 2: 128 -> 32 (tf32, 2-term, both weights in one pass) ----
    k_gemm_tc32<<<M / 128, 256, SMEM_TC32>>>(hB, wl2, wr2, xl, xr);
    k_aggr8c<<<2500, 256>>>(att2, we2, b2, xl, xr, hA);  // hA = emb [40][64000]

    // ---- LSTM input projection ----
    k_gates_tc<<<dim3(NCHUNK, 2), 256, SMEM_GATE>>>(hA, wih);
    k_gates_reduce<<<(1024 * GNUM + 255) / 256, 256>>>(bih, bhh);

    // ---- LSTM (persistent, all 10 steps) + head ----
    k_lstm_all<<<8, 128, SMEM_LSTM>>>();
    k_fc<<<1, 512>>>(fc1w, fc1b, fc2w, fc2b, (float*)d_out);
}